// round 15
// baseline (speedup 1.0000x reference)
#include <cuda_runtime.h>
#include <math.h>

#define NB 32
#define NG 50
#define NA 8400
#define NC 80
#define NCH 85
#define NBLK 33            // ceil(8400/256)
#define FLT_BIG 3.402823466e+38f

// -------- scratch (static device globals) --------
__device__ float4 d_box[NB*NA];
__device__ float  d_objl[NB*NA];
__device__ float  d_sobj[NB*NA];
__device__ unsigned long long d_geom[NB*NA];
__device__ unsigned int d_ball[NB*NBLK*8];
__device__ int    d_bcnt[NB*NBLK];
__device__ int    d_nfg[NB];
__device__ unsigned long long d_vmask[NB];
__device__ unsigned long long d_wantb[NB*2];     // 80-bit class-want mask, 2x u64

// compacted (sorted by anchor id)
__device__ int    d_fa[NB*NA];
__device__ float4 d_fbox[NB*NA];
__device__ float  d_fsobj[NB*NA];
__device__ unsigned long long d_fgeom[NB*NA];
__device__ float  d_s[NB*NA];
__device__ float  d_V[NB*NC*NA];                 // [b][c][j] (wanted classes only)
__device__ float2 d_ci[NB*NG*NA];                // (cost, iou)
__device__ float  d_thr[NB*NG];
__device__ double d_acc[4];

__device__ __forceinline__ void anchor_info(int a, int& H, float& fs, int& cell) {
    if (a < 6400)      { H = 80; fs = 8.f;  cell = a; }
    else if (a < 8000) { H = 40; fs = 16.f; cell = a - 6400; }
    else               { H = 20; fs = 32.f; cell = a - 8000; }
}
__device__ __forceinline__ const float* lvl_ptr(int a, const float* o0, const float* o1, const float* o2) {
    return a < 6400 ? o0 : (a < 8000 ? o1 : o2);
}
__device__ __forceinline__ double warp_sum(double v) {
    #pragma unroll
    for (int o = 16; o; o >>= 1) v += __shfl_down_sync(0xffffffffu, v, o);
    return v;
}
__device__ __forceinline__ void ins_min(float (&t)[10], float v) {
    #pragma unroll
    for (int i = 0; i < 10; ++i) { if (v < t[i]) { float tmp = t[i]; t[i] = v; v = tmp; } }
}
__device__ __forceinline__ void ins_max(float (&t)[10], float v) {
    #pragma unroll
    for (int i = 0; i < 10; ++i) { if (v > t[i]) { float tmp = t[i]; t[i] = v; v = tmp; } }
}

// -------- K0: vmask + want bitmask + zero accumulators --------
__global__ void k_init(const float* __restrict__ labels) {
    int b = blockIdx.x, t = threadIdx.x;
    __shared__ unsigned long long m, w0, w1;
    if (t == 0) {
        m = 0ull; w0 = 0ull; w1 = 0ull;
        d_nfg[b] = 0;
        if (b == 0) { d_acc[0]=0.0; d_acc[1]=0.0; d_acc[2]=0.0; d_acc[3]=0.0; }
    }
    __syncthreads();
    if (t < NG) {
        const float* L = labels + (b*NG + t)*5;
        float s = L[0]+L[1]+L[2]+L[3]+L[4];
        if (s > 0.f) {
            atomicOr(&m, 1ull << t);
            int cls = (int)L[0];
            if (cls < 64) atomicOr(&w0, 1ull << cls);
            else          atomicOr(&w1, 1ull << (cls - 64));
        }
    }
    __syncthreads();
    if (t == 0) {
        d_vmask[b] = m;
        d_wantb[b*2]   = w0;
        d_wantb[b*2+1] = w1;
    }
}

// -------- K1: decode + geometry (valid gts only) + fg ballots + dense obj BCE --------
__global__ void k_anchor(const float* __restrict__ o0, const float* __restrict__ o1,
                         const float* __restrict__ o2, const float* __restrict__ labels) {
    int b = blockIdx.y, blk = blockIdx.x, tid = threadIdx.x;
    int a = blk*256 + tid;
    __shared__ float Lx[NG], Ly[NG], Lw[NG], Lh[NG];
    __shared__ int wcnt[8];
    __shared__ double wobj[8];
    if (tid < NG) {
        const float* L = labels + (b*NG + tid)*5;
        Lx[tid] = L[1]; Ly[tid] = L[2]; Lw[tid] = L[3]; Lh[tid] = L[4];
    }
    __syncthreads();

    bool inrange = (a < NA);
    bool fgany = false;
    double objv = 0.0;
    if (inrange) {
        int H, cell; float fs;
        anchor_info(a, H, fs, cell);
        const float* o = lvl_ptr(a, o0, o1, o2);
        int chs = H*H;
        int base = b*NCH*chs + cell;
        float v0 = o[base], v1 = o[base+chs], v2 = o[base+2*chs],
              v3 = o[base+3*chs], v4 = o[base+4*chs];
        int x = cell % H, y = cell / H;
        float4 bx;
        bx.x = (v0 + (float)x)*fs;
        bx.y = (v1 + (float)y)*fs;
        bx.z = __expf(v2)*fs;
        bx.w = __expf(v3)*fs;
        int t = b*NA + a;
        d_box[t] = bx;
        d_objl[t] = v4;
        d_sobj[t] = __fdividef(1.f, 1.f + __expf(-v4));
        objv = (double)(fmaxf(v4, 0.f) + __logf(1.f + __expf(-fabsf(v4))));

        float cx = ((float)x + 0.5f)*fs, cy = ((float)y + 0.5f)*fs, rs = 2.5f*fs;
        unsigned long long geom = 0ull, vm = d_vmask[b];
        for (int g = 0; g < NG; ++g) {
            if (!((vm >> g) & 1ull)) continue;   // invalid gt: geom/fg never read
            float gx = Lx[g], gy = Ly[g], gw = Lw[g], gh = Lh[g];
            bool inb = (cx > gx - 0.5f*gw) && (cx < gx + 0.5f*gw) &&
                       (cy > gy - 0.5f*gh) && (cy < gy + 0.5f*gh);
            bool inc = (fabsf(cx - gx) < rs) && (fabsf(cy - gy) < rs);
            if (inb && inc) geom |= 1ull << g;
            if (inb || inc) fgany = true;
        }
        d_geom[t] = geom;
    }
    unsigned int word = __ballot_sync(0xffffffffu, fgany);
    int w = tid >> 5, lane = tid & 31;
    objv = warp_sum(objv);
    if (lane == 0) {
        d_ball[(b*NBLK + blk)*8 + w] = word;
        wcnt[w] = __popc(word);
        wobj[w] = objv;
    }
    __syncthreads();
    if (tid == 0) {
        int s = 0; double ob = 0.0;
        #pragma unroll
        for (int k = 0; k < 8; ++k) { s += wcnt[k]; ob += wobj[k]; }
        d_bcnt[b*NBLK + blk] = s;
        atomicAdd(&d_nfg[b], s);
        atomicAdd(&d_acc[1], ob);
    }
}

// -------- K2: globally ordered compaction --------
__global__ void k_compact() {
    int b = blockIdx.y, blk = blockIdx.x, tid = threadIdx.x;
    int w = tid >> 5, lane = tid & 31;
    __shared__ int woff[8];
    unsigned int word = d_ball[(b*NBLK + blk)*8 + w];
    __syncthreads();
    if (tid == 0) {
        int s = 0;
        for (int k = 0; k < blk; ++k) s += d_bcnt[b*NBLK + k];
        int r = s;
        for (int k = 0; k < 8; ++k) {
            woff[k] = r;
            r += __popc(d_ball[(b*NBLK + blk)*8 + k]);
        }
    }
    __syncthreads();
    if ((word >> lane) & 1u) {
        int j = woff[w] + __popc(word & ((1u << lane) - 1u));
        int a = blk*256 + tid;
        int t = b*NA + a;
        int fj = b*NA + j;
        d_fa[fj] = a;
        d_fbox[fj] = d_box[t];
        d_fsobj[fj] = d_sobj[t];
        d_fgeom[fj] = d_geom[t];
    }
}

// -------- K3: per fg anchor: s + V[c]; 20-wide load batching for MLP --------
__global__ void k_s(const float* __restrict__ o0, const float* __restrict__ o1,
                    const float* __restrict__ o2) {
    int b = blockIdx.y;
    int j = blockIdx.x*blockDim.x + threadIdx.x;
    if (j >= d_nfg[b]) return;
    unsigned long long w0 = d_wantb[b*2], w1 = d_wantb[b*2+1];
    int a = d_fa[b*NA + j];
    int H, cell; float fs;
    anchor_info(a, H, fs, cell);
    const float* o = lvl_ptr(a, o0, o1, o2);
    int chs = H*H;
    int base = (b*NCH + 5)*chs + cell;
    float sqs = sqrtf(d_fsobj[b*NA + j]);
    float s = 0.f;
    for (int c0 = 0; c0 < NC; c0 += 20) {
        float xl[20];
        #pragma unroll
        for (int k = 0; k < 20; ++k)           // 20 independent loads in flight
            xl[k] = o[base + (c0 + k)*chs];
        #pragma unroll
        for (int k = 0; k < 20; ++k) {
            int c = c0 + k;
            float e = __expf(-xl[k]);
            float p = sqs * rsqrtf(1.f + e);
            p = fminf(fmaxf(p, 1e-7f), 1.f - 1e-6f);
            float lm = __logf(1.f - p);
            s += lm;
            bool want = (c < 64) ? ((w0 >> c) & 1ull) : ((w1 >> (c - 64)) & 1ull);
            if (want)
                d_V[(b*NC + c)*NA + j] = lm - __logf(p);
        }
    }
    d_s[b*NA + j] = s;
}

// -------- K4: cost + iou; 4 blocks per row + 2-deep prefetch pipeline --------
__global__ void k_cost(const float* __restrict__ labels) {
    int b = blockIdx.y;
    int g = blockIdx.x >> 2;
    int q = blockIdx.x & 3;
    if (!((d_vmask[b] >> g) & 1ull)) return;
    const float* L = labels + (b*NG + g)*5;
    int cls = (int)L[0];
    float gx = L[1], gy = L[2], gw = L[3], gh = L[4];
    float ga = gw*gh;
    float gx0 = gx - 0.5f*gw, gx1 = gx + 0.5f*gw;
    float gy0 = gy - 0.5f*gh, gy1 = gy + 0.5f*gh;
    int n = d_nfg[b];
    int rowbase = (b*NG + g)*NA;
    const float4* fbox = d_fbox + b*NA;
    const float* Vrow = d_V + (b*NC + cls)*NA;
    const float* srow = d_s + b*NA;
    const unsigned long long* grow = d_fgeom + b*NA;

    int j = q*128 + threadIdx.x;
    if (j >= n) return;
    float4 bx = fbox[j];
    float Vj = Vrow[j], sj = srow[j];
    unsigned long long gj = grow[j];
    while (j < n) {
        int jn = j + 512;
        float4 bxn; float Vn, sn; unsigned long long gn;
        if (jn < n) {                         // prefetch next iteration
            bxn = fbox[jn]; Vn = Vrow[jn]; sn = srow[jn]; gn = grow[jn];
        }
        float px0 = bx.x - 0.5f*bx.z, px1 = bx.x + 0.5f*bx.z;
        float py0 = bx.y - 0.5f*bx.w, py1 = bx.y + 0.5f*bx.w;
        float tlx = fmaxf(gx0, px0), tly = fmaxf(gy0, py0);
        float brx = fminf(gx1, px1), bry = fminf(gy1, py1);
        float en = (tlx < brx && tly < bry) ? 1.f : 0.f;
        float inter = (brx - tlx)*(bry - tly)*en;
        float iou = inter / (ga + bx.z*bx.w - inter + 1e-12f);
        float geomterm = ((gj >> g) & 1ull) ? 0.f : 100000.f;
        float cost = Vj - sj - 3.f*__logf(iou + 1e-8f) + geomterm;
        float2 ci; ci.x = cost; ci.y = iou;
        d_ci[rowbase + j] = ci;
        bx = bxn; Vj = Vn; sj = sn; gj = gn;
        j = jn;
    }
}

// -------- K5: dyn_k + threshold; 4x float4 batched stream + early-reject --------
__global__ void k_thr() {
    int b = blockIdx.y, g = blockIdx.x;
    int gi = b*NG + g;
    int lane = threadIdx.x;
    if (!((d_vmask[b] >> g) & 1ull)) {
        if (lane == 0) d_thr[gi] = -FLT_BIG;
        return;
    }
    int n = d_nfg[b];
    float ti[10], tc[10];
    #pragma unroll
    for (int i = 0; i < 10; ++i) { ti[i] = 0.f; tc[i] = FLT_BIG; }
    const float2* row = d_ci + (size_t)gi*NA;
    const float4* row4 = (const float4*)row;
    int n2 = n >> 1;
    for (int j = lane; j < n2; j += 128) {
        float4 v[4];
        #pragma unroll
        for (int k = 0; k < 4; ++k) {          // 4 independent 16B loads in flight
            int jj = j + k*32;
            if (jj < n2) v[k] = row4[jj];
        }
        #pragma unroll
        for (int k = 0; k < 4; ++k) {          // process in original per-lane order
            int jj = j + k*32;
            if (jj < n2) {
                if (v[k].y > ti[9]) ins_max(ti, v[k].y);
                if (v[k].x < tc[9]) ins_min(tc, v[k].x);
                if (v[k].w > ti[9]) ins_max(ti, v[k].w);
                if (v[k].z < tc[9]) ins_min(tc, v[k].z);
            }
        }
    }
    if ((n & 1) && lane == 0) {
        float2 ci = row[n - 1];
        if (ci.y > ti[9]) ins_max(ti, ci.y);
        if (ci.x < tc[9]) ins_min(tc, ci.x);
    }
    #pragma unroll
    for (int off = 16; off >= 1; off >>= 1) {
        float ri[10], rc[10];
        #pragma unroll
        for (int i = 0; i < 10; ++i) {
            ri[i] = __shfl_down_sync(0xffffffffu, ti[i], off);
            rc[i] = __shfl_down_sync(0xffffffffu, tc[i], off);
        }
        #pragma unroll
        for (int i = 0; i < 10; ++i) {
            if (ri[i] > ti[9]) ins_max(ti, ri[i]);
            if (rc[i] < tc[9]) ins_min(tc, rc[i]);
        }
    }
    if (lane == 0) {
        float sum = 0.f;
        #pragma unroll
        for (int i = 0; i < 10; ++i) sum += ti[i];
        int dk = (int)sum;
        if (dk < 1) dk = 1;
        if (dk > 10) dk = 10;
        d_thr[gi] = tc[dk - 1];
    }
}

// -------- K6: final match + fg losses; two-phase scan + 8-wide class batching --------
__global__ void k_assign(const float* __restrict__ o0, const float* __restrict__ o1,
                         const float* __restrict__ o2, const float* __restrict__ labels) {
    int b = blockIdx.y;
    int j = blockIdx.x*blockDim.x + threadIdx.x;
    __shared__ float sthr[NG];
    if (threadIdx.x < NG) sthr[threadIdx.x] = d_thr[b*NG + threadIdx.x];
    __syncthreads();
    double li = 0.0, lo = 0.0, lc = 0.0, lf = 0.0;
    if (j < d_nfg[b]) {
        unsigned long long vm = d_vmask[b];
        const float2* cij = d_ci + (size_t)b*NG*NA + j;
        // phase 1: issue all guarded cost loads (high MLP)
        float cv[NG];
        #pragma unroll 10
        for (int g = 0; g < NG; ++g) {
            if ((vm >> g) & 1ull) cv[g] = cij[(size_t)g*NA].x;
        }
        // phase 2: compare logic in original order
        unsigned long long mmask = 0ull;
        int cnt = 0, bestg = 0;
        float best = FLT_BIG;
        for (int g = 0; g < NG; ++g) {
            if (!((vm >> g) & 1ull)) continue;
            float c = cv[g];
            if (c < best) { best = c; bestg = g; }
            if (c <= sthr[g]) { mmask |= 1ull << g; cnt++; }
        }
        if (cnt > 1) mmask &= (1ull << bestg);
        if (mmask) {
            int mgt = __ffsll((long long)mmask) - 1;
            int a = d_fa[b*NA + j];
            float piou = cij[(size_t)mgt*NA].y;
            lf = 1.0;
            lo = -(double)d_objl[b*NA + a];
            const float* L = labels + (b*NG + mgt)*5;
            float tx = L[1], ty = L[2], tw = L[3], th = L[4];
            float4 pb = d_fbox[b*NA + j];
            float tlx = fmaxf(pb.x - 0.5f*pb.z, tx - 0.5f*tw);
            float tly = fmaxf(pb.y - 0.5f*pb.w, ty - 0.5f*th);
            float brx = fminf(pb.x + 0.5f*pb.z, tx + 0.5f*tw);
            float bry = fminf(pb.y + 0.5f*pb.w, ty + 0.5f*th);
            float en = (tlx < brx && tly < bry) ? 1.f : 0.f;
            float iw = fmaxf(brx - tlx, 0.f), ih = fmaxf(bry - tly, 0.f);
            float inter = iw*ih*en;
            float uni = pb.z*pb.w + tw*th - inter + 1e-16f;
            float iou = inter/uni;
            li = (double)(1.f - iou*iou);
            int mcls = (int)L[0];
            int H, cell; float fs;
            anchor_info(a, H, fs, cell);
            const float* o = lvl_ptr(a, o0, o1, o2);
            int chs = H*H;
            int base = (b*NCH + 5)*chs + cell;
            float csum = 0.f;
            for (int c0 = 0; c0 < NC; c0 += 8) {
                float xl[8];
                #pragma unroll
                for (int k = 0; k < 8; ++k)
                    xl[k] = o[base + (c0 + k)*chs];
                #pragma unroll
                for (int k = 0; k < 8; ++k)
                    csum += fmaxf(xl[k], 0.f) + __logf(1.f + __expf(-fabsf(xl[k])));
            }
            csum -= o[base + mcls*chs] * piou;
            lc = (double)csum;
        }
    }
    li = warp_sum(li); lo = warp_sum(lo); lc = warp_sum(lc); lf = warp_sum(lf);
    if ((threadIdx.x & 31) == 0) {
        if (li != 0.0) atomicAdd(&d_acc[0], li);
        if (lo != 0.0) atomicAdd(&d_acc[1], lo);
        if (lc != 0.0) atomicAdd(&d_acc[2], lc);
        if (lf != 0.0) atomicAdd(&d_acc[3], lf);
    }
}

// -------- K7: combine --------
__global__ void k_final(float* out) {
    double nf = d_acc[3];
    if (nf < 1.0) nf = 1.0;
    out[0] = (float)((5.0*d_acc[0] + d_acc[1] + d_acc[2]) / nf);
}

extern "C" void kernel_launch(void* const* d_in, const int* in_sizes, int n_in,
                              void* d_out, int out_size) {
    const float* o0 = (const float*)d_in[0];
    const float* o1 = (const float*)d_in[1];
    const float* o2 = (const float*)d_in[2];
    const float* lb = (const float*)d_in[3];

    k_init<<<NB, 64>>>(lb);
    k_anchor<<<dim3(NBLK, NB), 256>>>(o0, o1, o2, lb);
    k_compact<<<dim3(NBLK, NB), 256>>>();
    k_s<<<dim3((NA + 127)/128, NB), 128>>>(o0, o1, o2);
    k_cost<<<dim3(NG*4, NB), 128>>>(lb);
    k_thr<<<dim3(NG, NB), 32>>>();
    k_assign<<<dim3((NA + 127)/128, NB), 128>>>(o0, o1, o2, lb);
    k_final<<<1, 1>>>((float*)d_out);
}

// round 16
// speedup vs baseline: 1.7666x; 1.7666x over previous
#include <cuda_runtime.h>
#include <math.h>

#define NB 32
#define NG 50
#define NA 8400
#define NC 80
#define NCH 85
#define NBLK 33            // ceil(8400/256)
#define FLT_BIG 3.402823466e+38f

// -------- scratch (static device globals) --------
__device__ float4 d_box[NB*NA];
__device__ float  d_objl[NB*NA];
__device__ float  d_sobj[NB*NA];
__device__ unsigned long long d_geom[NB*NA];
__device__ unsigned int d_ball[NB*NBLK*8];
__device__ int    d_bcnt[NB*NBLK];
__device__ int    d_nfg[NB];
__device__ unsigned long long d_vmask[NB];
__device__ unsigned long long d_wantb[NB*2];     // 80-bit class-want mask, 2x u64

// compacted (sorted by anchor id)
__device__ int    d_fa[NB*NA];
__device__ float4 d_fbox[NB*NA];
__device__ float  d_fsobj[NB*NA];
__device__ unsigned long long d_fgeom[NB*NA];
__device__ float  d_s[NB*NA];
__device__ float  d_V[NB*NC*NA];                 // [b][c][j] (wanted classes only)
__device__ float2 d_ci[NB*NG*NA];                // (cost, iou)
__device__ float  d_thr[NB*NG];
__device__ double d_acc[4];

__device__ __forceinline__ void anchor_info(int a, int& H, float& fs, int& cell) {
    if (a < 6400)      { H = 80; fs = 8.f;  cell = a; }
    else if (a < 8000) { H = 40; fs = 16.f; cell = a - 6400; }
    else               { H = 20; fs = 32.f; cell = a - 8000; }
}
__device__ __forceinline__ const float* lvl_ptr(int a, const float* o0, const float* o1, const float* o2) {
    return a < 6400 ? o0 : (a < 8000 ? o1 : o2);
}
__device__ __forceinline__ double warp_sum(double v) {
    #pragma unroll
    for (int o = 16; o; o >>= 1) v += __shfl_down_sync(0xffffffffu, v, o);
    return v;
}
__device__ __forceinline__ void ins_min(float (&t)[10], float v) {
    #pragma unroll
    for (int i = 0; i < 10; ++i) { if (v < t[i]) { float tmp = t[i]; t[i] = v; v = tmp; } }
}
__device__ __forceinline__ void ins_max(float (&t)[10], float v) {
    #pragma unroll
    for (int i = 0; i < 10; ++i) { if (v > t[i]) { float tmp = t[i]; t[i] = v; v = tmp; } }
}

// -------- K0: vmask + want bitmask + zero accumulators --------
__global__ void k_init(const float* __restrict__ labels) {
    int b = blockIdx.x, t = threadIdx.x;
    __shared__ unsigned long long m, w0, w1;
    if (t == 0) {
        m = 0ull; w0 = 0ull; w1 = 0ull;
        d_nfg[b] = 0;
        if (b == 0) { d_acc[0]=0.0; d_acc[1]=0.0; d_acc[2]=0.0; d_acc[3]=0.0; }
    }
    __syncthreads();
    if (t < NG) {
        const float* L = labels + (b*NG + t)*5;
        float s = L[0]+L[1]+L[2]+L[3]+L[4];
        if (s > 0.f) {
            atomicOr(&m, 1ull << t);
            int cls = (int)L[0];
            if (cls < 64) atomicOr(&w0, 1ull << cls);
            else          atomicOr(&w1, 1ull << (cls - 64));
        }
    }
    __syncthreads();
    if (t == 0) {
        d_vmask[b] = m;
        d_wantb[b*2]   = w0;
        d_wantb[b*2+1] = w1;
    }
}

// -------- K1: decode + geometry (valid gts only) + fg ballots + dense obj BCE --------
__global__ void k_anchor(const float* __restrict__ o0, const float* __restrict__ o1,
                         const float* __restrict__ o2, const float* __restrict__ labels) {
    int b = blockIdx.y, blk = blockIdx.x, tid = threadIdx.x;
    int a = blk*256 + tid;
    __shared__ float Lx[NG], Ly[NG], Lw[NG], Lh[NG];
    __shared__ int wcnt[8];
    __shared__ double wobj[8];
    if (tid < NG) {
        const float* L = labels + (b*NG + tid)*5;
        Lx[tid] = L[1]; Ly[tid] = L[2]; Lw[tid] = L[3]; Lh[tid] = L[4];
    }
    __syncthreads();

    bool inrange = (a < NA);
    bool fgany = false;
    double objv = 0.0;
    if (inrange) {
        int H, cell; float fs;
        anchor_info(a, H, fs, cell);
        const float* o = lvl_ptr(a, o0, o1, o2);
        int chs = H*H;
        int base = b*NCH*chs + cell;
        float v0 = o[base], v1 = o[base+chs], v2 = o[base+2*chs],
              v3 = o[base+3*chs], v4 = o[base+4*chs];
        int x = cell % H, y = cell / H;
        float4 bx;
        bx.x = (v0 + (float)x)*fs;
        bx.y = (v1 + (float)y)*fs;
        bx.z = __expf(v2)*fs;
        bx.w = __expf(v3)*fs;
        int t = b*NA + a;
        d_box[t] = bx;
        d_objl[t] = v4;
        d_sobj[t] = __fdividef(1.f, 1.f + __expf(-v4));
        objv = (double)(fmaxf(v4, 0.f) + __logf(1.f + __expf(-fabsf(v4))));

        float cx = ((float)x + 0.5f)*fs, cy = ((float)y + 0.5f)*fs, rs = 2.5f*fs;
        unsigned long long geom = 0ull, vm = d_vmask[b];
        for (int g = 0; g < NG; ++g) {
            if (!((vm >> g) & 1ull)) continue;   // invalid gt: geom/fg never read
            float gx = Lx[g], gy = Ly[g], gw = Lw[g], gh = Lh[g];
            bool inb = (cx > gx - 0.5f*gw) && (cx < gx + 0.5f*gw) &&
                       (cy > gy - 0.5f*gh) && (cy < gy + 0.5f*gh);
            bool inc = (fabsf(cx - gx) < rs) && (fabsf(cy - gy) < rs);
            if (inb && inc) geom |= 1ull << g;
            if (inb || inc) fgany = true;
        }
        d_geom[t] = geom;
    }
    unsigned int word = __ballot_sync(0xffffffffu, fgany);
    int w = tid >> 5, lane = tid & 31;
    objv = warp_sum(objv);
    if (lane == 0) {
        d_ball[(b*NBLK + blk)*8 + w] = word;
        wcnt[w] = __popc(word);
        wobj[w] = objv;
    }
    __syncthreads();
    if (tid == 0) {
        int s = 0; double ob = 0.0;
        #pragma unroll
        for (int k = 0; k < 8; ++k) { s += wcnt[k]; ob += wobj[k]; }
        d_bcnt[b*NBLK + blk] = s;
        atomicAdd(&d_nfg[b], s);
        atomicAdd(&d_acc[1], ob);
    }
}

// -------- K2: globally ordered compaction --------
__global__ void k_compact() {
    int b = blockIdx.y, blk = blockIdx.x, tid = threadIdx.x;
    int w = tid >> 5, lane = tid & 31;
    __shared__ int woff[8];
    unsigned int word = d_ball[(b*NBLK + blk)*8 + w];
    __syncthreads();
    if (tid == 0) {
        int s = 0;
        for (int k = 0; k < blk; ++k) s += d_bcnt[b*NBLK + k];
        int r = s;
        for (int k = 0; k < 8; ++k) {
            woff[k] = r;
            r += __popc(d_ball[(b*NBLK + blk)*8 + k]);
        }
    }
    __syncthreads();
    if ((word >> lane) & 1u) {
        int j = woff[w] + __popc(word & ((1u << lane) - 1u));
        int a = blk*256 + tid;
        int t = b*NA + a;
        int fj = b*NA + j;
        d_fa[fj] = a;
        d_fbox[fj] = d_box[t];
        d_fsobj[fj] = d_sobj[t];
        d_fgeom[fj] = d_geom[t];
    }
}

// -------- K3: per fg anchor: s + V[c]; 16-wide load batching for MLP --------
__global__ void k_s(const float* __restrict__ o0, const float* __restrict__ o1,
                    const float* __restrict__ o2) {
    int b = blockIdx.y;
    int j = blockIdx.x*blockDim.x + threadIdx.x;
    if (j >= d_nfg[b]) return;
    unsigned long long w0 = d_wantb[b*2], w1 = d_wantb[b*2+1];
    int a = d_fa[b*NA + j];
    int H, cell; float fs;
    anchor_info(a, H, fs, cell);
    const float* o = lvl_ptr(a, o0, o1, o2);
    int chs = H*H;
    int base = (b*NCH + 5)*chs + cell;
    float sqs = sqrtf(d_fsobj[b*NA + j]);
    float s = 0.f;
    for (int c0 = 0; c0 < NC; c0 += 16) {
        float xl[16];
        #pragma unroll
        for (int k = 0; k < 16; ++k)           // 16 independent loads in flight
            xl[k] = o[base + (c0 + k)*chs];
        #pragma unroll
        for (int k = 0; k < 16; ++k) {
            int c = c0 + k;
            float e = __expf(-xl[k]);
            float p = sqs * rsqrtf(1.f + e);
            p = fminf(fmaxf(p, 1e-7f), 1.f - 1e-6f);
            float lm = __logf(1.f - p);
            s += lm;
            bool want = (c < 64) ? ((w0 >> c) & 1ull) : ((w1 >> (c - 64)) & 1ull);
            if (want)
                d_V[(b*NC + c)*NA + j] = lm - __logf(p);
        }
    }
    d_s[b*NA + j] = s;
}

// -------- K4: cost + iou; 4 blocks per row + 2-deep prefetch pipeline --------
__global__ void k_cost(const float* __restrict__ labels) {
    int b = blockIdx.y;
    int g = blockIdx.x >> 2;
    int q = blockIdx.x & 3;
    if (!((d_vmask[b] >> g) & 1ull)) return;
    const float* L = labels + (b*NG + g)*5;
    int cls = (int)L[0];
    float gx = L[1], gy = L[2], gw = L[3], gh = L[4];
    float ga = gw*gh;
    float gx0 = gx - 0.5f*gw, gx1 = gx + 0.5f*gw;
    float gy0 = gy - 0.5f*gh, gy1 = gy + 0.5f*gh;
    int n = d_nfg[b];
    int rowbase = (b*NG + g)*NA;
    const float4* fbox = d_fbox + b*NA;
    const float* Vrow = d_V + (b*NC + cls)*NA;
    const float* srow = d_s + b*NA;
    const unsigned long long* grow = d_fgeom + b*NA;

    int j = q*128 + threadIdx.x;
    if (j >= n) return;
    float4 bx = fbox[j];
    float Vj = Vrow[j], sj = srow[j];
    unsigned long long gj = grow[j];
    while (j < n) {
        int jn = j + 512;
        float4 bxn; float Vn, sn; unsigned long long gn;
        if (jn < n) {                         // prefetch next iteration
            bxn = fbox[jn]; Vn = Vrow[jn]; sn = srow[jn]; gn = grow[jn];
        }
        float px0 = bx.x - 0.5f*bx.z, px1 = bx.x + 0.5f*bx.z;
        float py0 = bx.y - 0.5f*bx.w, py1 = bx.y + 0.5f*bx.w;
        float tlx = fmaxf(gx0, px0), tly = fmaxf(gy0, py0);
        float brx = fminf(gx1, px1), bry = fminf(gy1, py1);
        float en = (tlx < brx && tly < bry) ? 1.f : 0.f;
        float inter = (brx - tlx)*(bry - tly)*en;
        float iou = inter / (ga + bx.z*bx.w - inter + 1e-12f);
        float geomterm = ((gj >> g) & 1ull) ? 0.f : 100000.f;
        float cost = Vj - sj - 3.f*__logf(iou + 1e-8f) + geomterm;
        float2 ci; ci.x = cost; ci.y = iou;
        d_ci[rowbase + j] = ci;
        bx = bxn; Vj = Vn; sj = sn; gj = gn;
        j = jn;
    }
}

// -------- K5: dyn_k + threshold; 2x float4 scalar-batched stream + early-reject --------
__global__ void k_thr() {
    int b = blockIdx.y, g = blockIdx.x;
    int gi = b*NG + g;
    int lane = threadIdx.x;
    if (!((d_vmask[b] >> g) & 1ull)) {
        if (lane == 0) d_thr[gi] = -FLT_BIG;
        return;
    }
    int n = d_nfg[b];
    float ti[10], tc[10];
    #pragma unroll
    for (int i = 0; i < 10; ++i) { ti[i] = 0.f; tc[i] = FLT_BIG; }
    const float2* row = d_ci + (size_t)gi*NA;
    const float4* row4 = (const float4*)row;
    int n2 = n >> 1;
    int nb = n2 & ~63;                 // bulk: multiples of 64 float4s (2 per lane)
    for (int j = lane; j < nb; j += 64) {
        float4 va = row4[j];           // two independent 16B loads, no guards
        float4 vb = row4[j + 32];
        if (va.y > ti[9]) ins_max(ti, va.y);
        if (va.x < tc[9]) ins_min(tc, va.x);
        if (va.w > ti[9]) ins_max(ti, va.w);
        if (va.z < tc[9]) ins_min(tc, va.z);
        if (vb.y > ti[9]) ins_max(ti, vb.y);
        if (vb.x < tc[9]) ins_min(tc, vb.x);
        if (vb.w > ti[9]) ins_max(ti, vb.w);
        if (vb.z < tc[9]) ins_min(tc, vb.z);
    }
    for (int j = nb + lane; j < n2; j += 32) {   // remainder, proven 1-wide loop
        float4 v = row4[j];
        if (v.y > ti[9]) ins_max(ti, v.y);
        if (v.x < tc[9]) ins_min(tc, v.x);
        if (v.w > ti[9]) ins_max(ti, v.w);
        if (v.z < tc[9]) ins_min(tc, v.z);
    }
    if ((n & 1) && lane == 0) {
        float2 ci = row[n - 1];
        if (ci.y > ti[9]) ins_max(ti, ci.y);
        if (ci.x < tc[9]) ins_min(tc, ci.x);
    }
    #pragma unroll
    for (int off = 16; off >= 1; off >>= 1) {
        float ri[10], rc[10];
        #pragma unroll
        for (int i = 0; i < 10; ++i) {
            ri[i] = __shfl_down_sync(0xffffffffu, ti[i], off);
            rc[i] = __shfl_down_sync(0xffffffffu, tc[i], off);
        }
        #pragma unroll
        for (int i = 0; i < 10; ++i) {
            if (ri[i] > ti[9]) ins_max(ti, ri[i]);
            if (rc[i] < tc[9]) ins_min(tc, rc[i]);
        }
    }
    if (lane == 0) {
        float sum = 0.f;
        #pragma unroll
        for (int i = 0; i < 10; ++i) sum += ti[i];
        int dk = (int)sum;
        if (dk < 1) dk = 1;
        if (dk > 10) dk = 10;
        d_thr[gi] = tc[dk - 1];
    }
}

// -------- K6: final match + fg losses; 8-wide class-load batching --------
__global__ void k_assign(const float* __restrict__ o0, const float* __restrict__ o1,
                         const float* __restrict__ o2, const float* __restrict__ labels) {
    int b = blockIdx.y;
    int j = blockIdx.x*blockDim.x + threadIdx.x;
    __shared__ float sthr[NG];
    if (threadIdx.x < NG) sthr[threadIdx.x] = d_thr[b*NG + threadIdx.x];
    __syncthreads();
    double li = 0.0, lo = 0.0, lc = 0.0, lf = 0.0;
    if (j < d_nfg[b]) {
        unsigned long long vm = d_vmask[b];
        unsigned long long mmask = 0ull;
        int cnt = 0, bestg = 0;
        float best = FLT_BIG;
        const float2* cij = d_ci + (size_t)b*NG*NA + j;
        for (int g = 0; g < NG; ++g) {
            if (!((vm >> g) & 1ull)) continue;
            float c = cij[(size_t)g*NA].x;
            if (c < best) { best = c; bestg = g; }
            if (c <= sthr[g]) { mmask |= 1ull << g; cnt++; }
        }
        if (cnt > 1) mmask &= (1ull << bestg);
        if (mmask) {
            int mgt = __ffsll((long long)mmask) - 1;
            int a = d_fa[b*NA + j];
            float piou = cij[(size_t)mgt*NA].y;
            lf = 1.0;
            lo = -(double)d_objl[b*NA + a];
            const float* L = labels + (b*NG + mgt)*5;
            float tx = L[1], ty = L[2], tw = L[3], th = L[4];
            float4 pb = d_fbox[b*NA + j];
            float tlx = fmaxf(pb.x - 0.5f*pb.z, tx - 0.5f*tw);
            float tly = fmaxf(pb.y - 0.5f*pb.w, ty - 0.5f*th);
            float brx = fminf(pb.x + 0.5f*pb.z, tx + 0.5f*tw);
            float bry = fminf(pb.y + 0.5f*pb.w, ty + 0.5f*th);
            float en = (tlx < brx && tly < bry) ? 1.f : 0.f;
            float iw = fmaxf(brx - tlx, 0.f), ih = fmaxf(bry - tly, 0.f);
            float inter = iw*ih*en;
            float uni = pb.z*pb.w + tw*th - inter + 1e-16f;
            float iou = inter/uni;
            li = (double)(1.f - iou*iou);
            int mcls = (int)L[0];
            int H, cell; float fs;
            anchor_info(a, H, fs, cell);
            const float* o = lvl_ptr(a, o0, o1, o2);
            int chs = H*H;
            int base = (b*NCH + 5)*chs + cell;
            float csum = 0.f;
            for (int c0 = 0; c0 < NC; c0 += 8) {
                float xl[8];
                #pragma unroll
                for (int k = 0; k < 8; ++k)
                    xl[k] = o[base + (c0 + k)*chs];
                #pragma unroll
                for (int k = 0; k < 8; ++k)
                    csum += fmaxf(xl[k], 0.f) + __logf(1.f + __expf(-fabsf(xl[k])));
            }
            csum -= o[base + mcls*chs] * piou;
            lc = (double)csum;
        }
    }
    li = warp_sum(li); lo = warp_sum(lo); lc = warp_sum(lc); lf = warp_sum(lf);
    if ((threadIdx.x & 31) == 0) {
        if (li != 0.0) atomicAdd(&d_acc[0], li);
        if (lo != 0.0) atomicAdd(&d_acc[1], lo);
        if (lc != 0.0) atomicAdd(&d_acc[2], lc);
        if (lf != 0.0) atomicAdd(&d_acc[3], lf);
    }
}

// -------- K7: combine --------
__global__ void k_final(float* out) {
    double nf = d_acc[3];
    if (nf < 1.0) nf = 1.0;
    out[0] = (float)((5.0*d_acc[0] + d_acc[1] + d_acc[2]) / nf);
}

extern "C" void kernel_launch(void* const* d_in, const int* in_sizes, int n_in,
                              void* d_out, int out_size) {
    const float* o0 = (const float*)d_in[0];
    const float* o1 = (const float*)d_in[1];
    const float* o2 = (const float*)d_in[2];
    const float* lb = (const float*)d_in[3];

    k_init<<<NB, 64>>>(lb);
    k_anchor<<<dim3(NBLK, NB), 256>>>(o0, o1, o2, lb);
    k_compact<<<dim3(NBLK, NB), 256>>>();
    k_s<<<dim3((NA + 127)/128, NB), 128>>>(o0, o1, o2);
    k_cost<<<dim3(NG*4, NB), 128>>>(lb);
    k_thr<<<dim3(NG, NB), 32>>>();
    k_assign<<<dim3((NA + 127)/128, NB), 128>>>(o0, o1, o2, lb);
    k_final<<<1, 1>>>((float*)d_out);
}